// round 3
// baseline (speedup 1.0000x reference)
#include <cuda_runtime.h>
#include <math.h>

#define NB 2
#define CC 256
#define RCQ 32
#define HH 64
#define WW 64
#define HWP 4096   // H*W
#define C2 512     // 2*C

// ---------------- scratch (device globals; no allocation allowed) ----------------
__device__ float g_rq[NB * RCQ * HWP];
__device__ float g_rk[NB * RCQ * HWP];
__device__ float g_dq[NB * RCQ * HWP];
__device__ float g_dk[NB * RCQ * HWP];
__device__ float g_rv[NB * CC * HWP];
__device__ float g_dv[NB * CC * HWP];
__device__ float g_br[NB * CC * HWP];
__device__ float g_bd[NB * CC * HWP];
__device__ float g_S[(size_t)NB * HWP * HWP];   // 134 MB, reused for both attentions
__device__ float g_invZ[NB * HWP];
__device__ float g_gate[NB * CC * HWP];
__device__ float g_f[NB * C2 * HWP];
__device__ float g_y1[NB * C2 * HWP];
__device__ float g_y2[NB * C2 * HWP];

// ---------------- generic tiled fp32 GEMM: C[M,N] = A[M,K] @ B[K,N] (+bias,+res,*invZ) ----
// A row-major with leading dim lda; B row-major ldb; C row-major ldc=N.
// SCALEA: A[m,k] is multiplied by invZ[k] on load (per-batch invZ, stride K).
// RES: adds res[m*N+n] (per-batch stride sC). ACCUM: C += result. ACT: 0 none, 1 relu.
template <bool ACCUM, int ACT, bool SCALEA, bool RES, bool BIAS>
__global__ void __launch_bounds__(256) gemm_k(
    const float* __restrict__ A, int lda, size_t sA,
    const float* __restrict__ B, int ldb, size_t sB,
    float* __restrict__ C, size_t sC,
    const float* __restrict__ bias,
    const float* __restrict__ res,
    const float* __restrict__ invZ,
    int M, int N, int K)
{
    const int BM = 128, BN = 128, BK = 8, TM = 8, TN = 8;
    int bz = blockIdx.z;
    A += (size_t)bz * sA;
    B += (size_t)bz * sB;
    C += (size_t)bz * sC;
    const float* resp = RES ? res + (size_t)bz * sC : nullptr;
    const float* izp  = SCALEA ? invZ + (size_t)bz * (size_t)K : nullptr;

    __shared__ float As[BK][BM];
    __shared__ float Bs[BK][BN];

    int tid = threadIdx.x;
    int tx = tid % 16, ty = tid / 16;
    int m0 = blockIdx.y * BM, n0 = blockIdx.x * BN;

    // A tile loads: 128x8, 4 contiguous k per thread
    int arow = tid >> 1;
    int acol = (tid & 1) * 4;
    // B tile loads: 8x128, 4 contiguous n per thread
    int brow = tid >> 5;
    int bcol = (tid & 31) * 4;

    float acc[TM][TN];
#pragma unroll
    for (int i = 0; i < TM; i++)
#pragma unroll
        for (int j = 0; j < TN; j++) acc[i][j] = 0.f;

    for (int k0 = 0; k0 < K; k0 += BK) {
#pragma unroll
        for (int i = 0; i < 4; i++) {
            int m = m0 + arow;
            int k = k0 + acol + i;
            float v = 0.f;
            if (m < M && k < K) {
                v = A[(size_t)m * lda + k];
                if (SCALEA) v *= izp[k];
            }
            As[acol + i][arow] = v;
        }
#pragma unroll
        for (int i = 0; i < 4; i++) {
            int k = k0 + brow;
            int n = n0 + bcol + i;
            float v = 0.f;
            if (k < K && n < N) v = B[(size_t)k * ldb + n];
            Bs[brow][bcol + i] = v;
        }
        __syncthreads();
#pragma unroll
        for (int kk = 0; kk < BK; kk++) {
            float a[TM], b[TN];
#pragma unroll
            for (int i = 0; i < TM; i++) a[i] = As[kk][ty * TM + i];
#pragma unroll
            for (int j = 0; j < TN; j++) b[j] = Bs[kk][tx * TN + j];
#pragma unroll
            for (int i = 0; i < TM; i++)
#pragma unroll
                for (int j = 0; j < TN; j++) acc[i][j] += a[i] * b[j];
        }
        __syncthreads();
    }

#pragma unroll
    for (int i = 0; i < TM; i++) {
        int m = m0 + ty * TM + i;
        if (m >= M) continue;
        float bv = BIAS ? bias[m] : 0.f;
#pragma unroll
        for (int j = 0; j < TN; j++) {
            int n = n0 + tx * TN + j;
            if (n >= N) continue;
            size_t idx = (size_t)m * N + n;
            float v = acc[i][j] + bv;
            if (RES) v += resp[idx];
            if (ACCUM) v += C[idx];
            if (ACT == 1) v = fmaxf(v, 0.f);
            C[idx] = v;
        }
    }
}

// ---------------- attention logits + exp: S[i,j] = exp(sum_r Q[r,i]*K[r,j]) ----------------
__global__ void __launch_bounds__(256) attn_exp_k(
    const float* __restrict__ Q, const float* __restrict__ Km, float* __restrict__ S)
{
    int bz = blockIdx.z;
    Q  += (size_t)bz * RCQ * HWP;
    Km += (size_t)bz * RCQ * HWP;
    S  += (size_t)bz * HWP * (size_t)HWP;

    __shared__ float Qs[RCQ][64];
    __shared__ float Ks[RCQ][64];

    int i0 = blockIdx.y * 64, j0 = blockIdx.x * 64;
    int tid = threadIdx.x;
    for (int t = tid; t < RCQ * 64; t += 256) {
        int r = t >> 6, c = t & 63;
        Qs[r][c] = Q[(size_t)r * HWP + i0 + c];
        Ks[r][c] = Km[(size_t)r * HWP + j0 + c];
    }
    __syncthreads();

    int tx = tid % 16, ty = tid / 16;
    float acc[4][4];
#pragma unroll
    for (int i = 0; i < 4; i++)
#pragma unroll
        for (int j = 0; j < 4; j++) acc[i][j] = 0.f;

#pragma unroll
    for (int r = 0; r < RCQ; r++) {
        float q[4], k[4];
#pragma unroll
        for (int i = 0; i < 4; i++) q[i] = Qs[r][ty * 4 + i];
#pragma unroll
        for (int j = 0; j < 4; j++) k[j] = Ks[r][tx * 4 + j];
#pragma unroll
        for (int i = 0; i < 4; i++)
#pragma unroll
            for (int j = 0; j < 4; j++) acc[i][j] += q[i] * k[j];
    }
#pragma unroll
    for (int i = 0; i < 4; i++) {
        size_t row = (size_t)(i0 + ty * 4 + i) * HWP + j0 + tx * 4;
#pragma unroll
        for (int j = 0; j < 4; j++) S[row + j] = __expf(acc[i][j]);
    }
}

// ---------------- row sum -> 1/Z ----------------
__global__ void __launch_bounds__(256) rowsum_inv_k(
    const float* __restrict__ S, float* __restrict__ invZ)
{
    int i = blockIdx.x;
    int bz = blockIdx.y;
    const float* row = S + (size_t)bz * HWP * HWP + (size_t)i * HWP;
    float s = 0.f;
    for (int j = threadIdx.x; j < HWP; j += 256) s += row[j];
    __shared__ float red[256];
    red[threadIdx.x] = s;
    __syncthreads();
    for (int o = 128; o > 0; o >>= 1) {
        if (threadIdx.x < o) red[threadIdx.x] += red[threadIdx.x + o];
        __syncthreads();
    }
    if (threadIdx.x == 0) invZ[bz * HWP + i] = 1.f / red[0];
}

// ---------------- gated combine: f = [br*g + bd*(1-g); br*bd], g = sigmoid(gate_pre) ------
__global__ void __launch_bounds__(256) combine_k(
    const float* __restrict__ br, const float* __restrict__ bd,
    const float* __restrict__ gpre, float* __restrict__ f)
{
    size_t idx = (size_t)blockIdx.x * 256 + threadIdx.x;  // over NB*CC*HWP
    size_t n = idx / ((size_t)CC * HWP);
    size_t r = idx % ((size_t)CC * HWP);
    float a = br[idx], b = bd[idx];
    float g = 1.f / (1.f + __expf(-gpre[idx]));
    size_t base = n * (size_t)C2 * HWP;
    f[base + r] = a * g + b * (1.f - g);
    f[base + (size_t)CC * HWP + r] = a * b;
}

// ---------------- direct 3x3 conv, 512->512, SAME pad, relu+bias fused ----------------
// Block: 64 out channels x one image row (64 px). Each thread: 8 oc x 2 px.
__global__ void __launch_bounds__(256) conv3x3_k(
    const float* __restrict__ in, const float* __restrict__ w,
    const float* __restrict__ bias, float* __restrict__ out)
{
    const int CIN = C2, CK = 8, TO = 64;
    int octile = blockIdx.x;   // 0..7
    int y = blockIdx.y;        // 0..63
    int n = blockIdx.z;
    int tid = threadIdx.x;
    int xp = tid & 31;         // x-pair index
    int ocg = tid >> 5;        // 0..7
    int x0 = xp * 2;
    int oc0 = octile * TO;

    __shared__ float ws[CK][TO][9];
    __shared__ float is[CK][3][66];

    float acc[8][2];
#pragma unroll
    for (int o = 0; o < 8; o++) { acc[o][0] = 0.f; acc[o][1] = 0.f; }

    for (int ci0 = 0; ci0 < CIN; ci0 += CK) {
        for (int t = tid; t < CK * TO * 9; t += 256) {
            int oc = t / (CK * 9);
            int rem = t % (CK * 9);
            int ci = rem / 9, tap = rem % 9;
            ws[ci][oc][tap] = w[((size_t)(oc0 + oc) * CIN + ci0 + ci) * 9 + tap];
        }
        for (int t = tid; t < CK * 3 * 66; t += 256) {
            int ci = t / 198;
            int rem = t % 198;
            int ry = rem / 66;
            int sx = rem % 66;
            int xx = sx - 1;
            int yy = y + ry - 1;
            float v = 0.f;
            if (yy >= 0 && yy < HH && xx >= 0 && xx < WW)
                v = in[(((size_t)n * CIN + ci0 + ci) * HH + yy) * WW + xx];
            is[ci][ry][sx] = v;
        }
        __syncthreads();
#pragma unroll
        for (int ci = 0; ci < CK; ci++) {
            float iv[3][4];
#pragma unroll
            for (int ry = 0; ry < 3; ry++)
#pragma unroll
                for (int dx = 0; dx < 4; dx++) iv[ry][dx] = is[ci][ry][x0 + dx];
#pragma unroll
            for (int o = 0; o < 8; o++) {
                const float* wp = ws[ci][ocg * 8 + o];
#pragma unroll
                for (int ky = 0; ky < 3; ky++)
#pragma unroll
                    for (int kx = 0; kx < 3; kx++) {
                        float wv = wp[ky * 3 + kx];
                        acc[o][0] += wv * iv[ky][kx];
                        acc[o][1] += wv * iv[ky][kx + 1];
                    }
            }
        }
        __syncthreads();
    }
#pragma unroll
    for (int o = 0; o < 8; o++) {
        int oc = oc0 + ocg * 8 + o;
        float b = bias[oc];
        float v0 = fmaxf(acc[o][0] + b, 0.f);
        float v1 = fmaxf(acc[o][1] + b, 0.f);
        size_t base = (((size_t)n * CIN + oc) * HH + y) * WW + x0;
        out[base] = v0;
        out[base + 1] = v1;
    }
}

// ---------------- host launcher ----------------
extern "C" void kernel_launch(void* const* d_in, const int* in_sizes, int n_in,
                              void* d_out, int out_size)
{
    const float* rgb  = (const float*)d_in[0];
    const float* chm  = (const float*)d_in[1];
    const float* rq_w = (const float*)d_in[2];  const float* rq_b = (const float*)d_in[3];
    const float* rk_w = (const float*)d_in[4];  const float* rk_b = (const float*)d_in[5];
    const float* rv_w = (const float*)d_in[6];  const float* rv_b = (const float*)d_in[7];
    const float* dq_w = (const float*)d_in[8];  const float* dq_b = (const float*)d_in[9];
    const float* dk_w = (const float*)d_in[10]; const float* dk_b = (const float*)d_in[11];
    const float* dv_w = (const float*)d_in[12]; const float* dv_b = (const float*)d_in[13];
    const float* gate_w = (const float*)d_in[14]; const float* gate_b = (const float*)d_in[15];
    const float* fus1_w = (const float*)d_in[16]; const float* fus1_b = (const float*)d_in[17];
    const float* fus2_w = (const float*)d_in[18]; const float* fus2_b = (const float*)d_in[19];
    const float* fus3_w = (const float*)d_in[20]; const float* fus3_b = (const float*)d_in[21];
    const float* skip_w = (const float*)d_in[22]; const float* skip_b = (const float*)d_in[23];
    float* out = (float*)d_out;

    float *rq, *rk, *dq, *dk, *rv, *dv, *br, *bd, *S, *invZ, *gate, *f, *y1, *y2;
    cudaGetSymbolAddress((void**)&rq, g_rq);
    cudaGetSymbolAddress((void**)&rk, g_rk);
    cudaGetSymbolAddress((void**)&dq, g_dq);
    cudaGetSymbolAddress((void**)&dk, g_dk);
    cudaGetSymbolAddress((void**)&rv, g_rv);
    cudaGetSymbolAddress((void**)&dv, g_dv);
    cudaGetSymbolAddress((void**)&br, g_br);
    cudaGetSymbolAddress((void**)&bd, g_bd);
    cudaGetSymbolAddress((void**)&S, g_S);
    cudaGetSymbolAddress((void**)&invZ, g_invZ);
    cudaGetSymbolAddress((void**)&gate, g_gate);
    cudaGetSymbolAddress((void**)&f, g_f);
    cudaGetSymbolAddress((void**)&y1, g_y1);
    cudaGetSymbolAddress((void**)&y2, g_y2);

    dim3 blk(256);
    auto grid_mn = [](int M, int N) {
        return dim3((unsigned)((N + 127) / 128), (unsigned)((M + 127) / 128), NB);
    };
    const size_t sX = (size_t)CC * HWP;       // per-batch stride of C-channel tensors
    const size_t sQ = (size_t)RCQ * HWP;      // per-batch stride of rc-channel tensors
    const size_t sS = (size_t)HWP * HWP;      // per-batch stride of attention scratch
    const size_t sF = (size_t)C2 * HWP;       // per-batch stride of 2C-channel tensors

    // --- projections (1x1 convs as GEMMs) ---
    gemm_k<false, 0, false, false, true><<<grid_mn(RCQ, HWP), blk>>>(
        rq_w, CC, 0, rgb, HWP, sX, rq, sQ, rq_b, nullptr, nullptr, RCQ, HWP, CC);
    gemm_k<false, 0, false, false, true><<<grid_mn(RCQ, HWP), blk>>>(
        rk_w, CC, 0, rgb, HWP, sX, rk, sQ, rk_b, nullptr, nullptr, RCQ, HWP, CC);
    gemm_k<false, 0, false, false, true><<<grid_mn(CC, HWP), blk>>>(
        rv_w, CC, 0, rgb, HWP, sX, rv, sX, rv_b, nullptr, nullptr, CC, HWP, CC);
    gemm_k<false, 0, false, false, true><<<grid_mn(RCQ, HWP), blk>>>(
        dq_w, CC, 0, chm, HWP, sX, dq, sQ, dq_b, nullptr, nullptr, RCQ, HWP, CC);
    gemm_k<false, 0, false, false, true><<<grid_mn(RCQ, HWP), blk>>>(
        dk_w, CC, 0, chm, HWP, sX, dk, sQ, dk_b, nullptr, nullptr, RCQ, HWP, CC);
    gemm_k<false, 0, false, false, true><<<grid_mn(CC, HWP), blk>>>(
        dv_w, CC, 0, chm, HWP, sX, dv, sX, dv_b, nullptr, nullptr, CC, HWP, CC);

    // --- attention R: rgb_attn = softmax(dq.dk), br = rv @ attn + rgb ---
    attn_exp_k<<<dim3(64, 64, NB), blk>>>(dq, dk, S);
    rowsum_inv_k<<<dim3(HWP, NB), blk>>>(S, invZ);
    gemm_k<false, 0, true, true, false><<<grid_mn(CC, HWP), blk>>>(
        rv, HWP, sX, S, HWP, sS, br, sX, nullptr, rgb, invZ, CC, HWP, HWP);

    // --- attention D: depth_attn = softmax(rq.rk), bd = dv @ attn + chm ---
    attn_exp_k<<<dim3(64, 64, NB), blk>>>(rq, rk, S);
    rowsum_inv_k<<<dim3(HWP, NB), blk>>>(S, invZ);
    gemm_k<false, 0, true, true, false><<<grid_mn(CC, HWP), blk>>>(
        dv, HWP, sX, S, HWP, sS, bd, sX, nullptr, chm, invZ, CC, HWP, HWP);

    // --- gate pre-activation: gate = Wg[:, :C] @ br + Wg[:, C:] @ bd + bg ---
    gemm_k<false, 0, false, false, true><<<grid_mn(CC, HWP), blk>>>(
        gate_w, C2, 0, br, HWP, sX, gate, sX, gate_b, nullptr, nullptr, CC, HWP, CC);
    gemm_k<true, 0, false, false, false><<<grid_mn(CC, HWP), blk>>>(
        gate_w + CC, C2, 0, bd, HWP, sX, gate, sX, nullptr, nullptr, nullptr, CC, HWP, CC);

    // --- gated fusion -> f = [c_fused; d_fused] ---
    combine_k<<<(unsigned)((size_t)NB * CC * HWP / 256), blk>>>(br, bd, gate, f);

    // --- fus1: y1 = relu(W1 @ f + b1) ---
    gemm_k<false, 1, false, false, true><<<grid_mn(C2, HWP), blk>>>(
        fus1_w, C2, 0, f, HWP, sF, y1, sF, fus1_b, nullptr, nullptr, C2, HWP, C2);

    // --- fus2: y2 = relu(conv3x3(y1) + b2) ---
    conv3x3_k<<<dim3(8, HH, NB), blk>>>(y1, fus2_w, fus2_b, y2);

    // --- head: out = W3 @ y2 + b3 + Wskip @ f + bskip ---
    gemm_k<false, 0, false, false, true><<<grid_mn(CC, HWP), blk>>>(
        fus3_w, C2, 0, y2, HWP, sF, out, sX, fus3_b, nullptr, nullptr, CC, HWP, C2);
    gemm_k<true, 0, false, false, true><<<grid_mn(CC, HWP), blk>>>(
        skip_w, C2, 0, f, HWP, sF, out, sX, skip_b, nullptr, nullptr, CC, HWP, C2);

    (void)in_sizes; (void)n_in; (void)out_size;
}

// round 4
// speedup vs baseline: 4.0393x; 4.0393x over previous
#include <cuda_runtime.h>
#include <cstdint>
#include <math.h>

#define NB 2
#define CC 256
#define RCQ 32
#define HH 64
#define WW 64
#define HWP 4096   // H*W
#define C2 512     // 2*C
#define KCOL 4608  // 512*9 (im2col K)

// ---------------- scratch (device globals; no allocation allowed) ----------------
__device__ float g_rq[NB * RCQ * HWP];
__device__ float g_rk[NB * RCQ * HWP];
__device__ float g_dq[NB * RCQ * HWP];
__device__ float g_dk[NB * RCQ * HWP];
__device__ float g_rv[NB * CC * HWP];
__device__ float g_dv[NB * CC * HWP];
__device__ float g_S[(size_t)NB * HWP * HWP];     // 134 MB, reused for both attentions
__device__ float g_invZ[NB * HWP];
__device__ float g_cat[(size_t)NB * C2 * HWP];    // [br ; bd]
__device__ float g_gate[(size_t)NB * CC * HWP];
__device__ float g_f[(size_t)NB * C2 * HWP];
__device__ float g_y1[(size_t)NB * C2 * HWP];
__device__ float g_y2[(size_t)NB * C2 * HWP];
__device__ float g_col[(size_t)NB * KCOL * HWP];  // im2col buffer (151 MB)

// ---------------- TF32 tensor-core GEMM ----------------
// C[M,N] = A[M,K] @ B[K,N]; A row-major lda, B row-major ldb, C row-major ldc=N.
// Block tile 128x128, BK=32, 8 warps (each 64x32), mma.m16n8k8.tf32, cp.async 2-stage.
// Requirements: N % 128 == 0, K % 32 == 0 (holds for all uses). M guarded.

#define ASTR 36               // 36 % 32 == 4 -> conflict-free A-frag LDS
#define BSTR 136              // 136 % 32 == 8 -> conflict-free B-frag LDS
#define ABUF (128 * ASTR)     // floats per A stage
#define BBUF (32 * BSTR)      // floats per B stage
#define SMEM_BYTES ((2 * ABUF + 2 * BBUF) * 4)   // 71680

__device__ __forceinline__ void cp16(uint32_t dst, const void* src, bool v) {
    int sz = v ? 16 : 0;
    asm volatile("cp.async.cg.shared.global [%0], [%1], 16, %2;\n"
                 :: "r"(dst), "l"(src), "r"(sz));
}
__device__ __forceinline__ uint32_t cvt_tf32(float x) {
    uint32_t r;
    asm("cvt.rna.tf32.f32 %0, %1;" : "=r"(r) : "f"(x));
    return r;
}
__device__ __forceinline__ void mma8(float* c, const uint32_t* a, uint32_t b0, uint32_t b1) {
    asm volatile(
        "mma.sync.aligned.m16n8k8.row.col.f32.tf32.tf32.f32 "
        "{%0,%1,%2,%3}, {%4,%5,%6,%7}, {%8,%9}, {%0,%1,%2,%3};"
        : "+f"(c[0]), "+f"(c[1]), "+f"(c[2]), "+f"(c[3])
        : "r"(a[0]), "r"(a[1]), "r"(a[2]), "r"(a[3]), "r"(b0), "r"(b1));
}

template <bool ACCUM, int ACT, bool RES, bool BIAS>
__global__ void __launch_bounds__(256) tgemm_k(
    const float* __restrict__ A, int lda, size_t sA,
    const float* __restrict__ B, int ldb, size_t sB,
    float* __restrict__ C, size_t sC,
    const float* __restrict__ bias,
    const float* __restrict__ res, size_t sRes,
    int M, int N, int K)
{
    extern __shared__ float sm[];
    int bz = blockIdx.z;
    A += (size_t)bz * sA;
    B += (size_t)bz * sB;
    C += (size_t)bz * sC;
    const float* resp = RES ? res + (size_t)bz * sRes : nullptr;

    const int m0 = blockIdx.y * 128, n0 = blockIdx.x * 128;
    const int tid = threadIdx.x;
    const int lane = tid & 31, warp = tid >> 5;
    const int g = lane >> 2, t4 = lane & 3;
    const int wm = (warp >> 2) * 64;
    const int wn = (warp & 3) * 32;

    const uint32_t sbase = (uint32_t)__cvta_generic_to_shared(sm);

    float acc[4][4][4];
#pragma unroll
    for (int mt = 0; mt < 4; mt++)
#pragma unroll
        for (int nt = 0; nt < 4; nt++)
#pragma unroll
            for (int i = 0; i < 4; i++) acc[mt][nt][i] = 0.f;

    auto loadA = [&](int buf, int k0) {
#pragma unroll
        for (int i = 0; i < 4; i++) {
            int c = tid + i * 256;          // 1024 16B-chunks: 128 rows x 8 kgroups
            int m = c >> 3, kg = c & 7;
            bool v = (m0 + m) < M;
            int mm = v ? (m0 + m) : 0;
            const float* src = A + (size_t)mm * lda + k0 + kg * 4;
            uint32_t dst = sbase + (uint32_t)((buf * ABUF + m * ASTR + kg * 4) * 4);
            cp16(dst, src, v);
        }
    };
    auto loadB = [&](int buf, int k0) {
#pragma unroll
        for (int i = 0; i < 4; i++) {
            int c = tid + i * 256;          // 1024 chunks: 32 k-rows x 32 ngroups
            int k = c >> 5, ng = c & 31;
            const float* src = B + (size_t)(k0 + k) * ldb + n0 + ng * 4;
            uint32_t dst = sbase + (uint32_t)((2 * ABUF + buf * BBUF + k * BSTR + ng * 4) * 4);
            cp16(dst, src, true);
        }
    };

    const int KT = K / 32;
    loadA(0, 0);
    loadB(0, 0);
    asm volatile("cp.async.commit_group;\n");

    int cur = 0;
    for (int kt = 0; kt < KT; kt++) {
        if (kt + 1 < KT) {
            loadA(cur ^ 1, (kt + 1) * 32);
            loadB(cur ^ 1, (kt + 1) * 32);
            asm volatile("cp.async.commit_group;\n");
            asm volatile("cp.async.wait_group 1;\n");
        } else {
            asm volatile("cp.async.wait_group 0;\n");
        }
        __syncthreads();

        const float* Ab = sm + cur * ABUF;
        const float* Bb = sm + 2 * ABUF + cur * BBUF;
#pragma unroll
        for (int ks = 0; ks < 4; ks++) {
            const int kk = ks * 8;
            uint32_t af[4][4];
#pragma unroll
            for (int mt = 0; mt < 4; mt++) {
                int r0 = wm + mt * 16 + g;
                af[mt][0] = cvt_tf32(Ab[r0 * ASTR + kk + t4]);
                af[mt][1] = cvt_tf32(Ab[(r0 + 8) * ASTR + kk + t4]);
                af[mt][2] = cvt_tf32(Ab[r0 * ASTR + kk + t4 + 4]);
                af[mt][3] = cvt_tf32(Ab[(r0 + 8) * ASTR + kk + t4 + 4]);
            }
#pragma unroll
            for (int nt = 0; nt < 4; nt++) {
                int cb = wn + nt * 8 + g;
                uint32_t b0 = cvt_tf32(Bb[(kk + t4) * BSTR + cb]);
                uint32_t b1 = cvt_tf32(Bb[(kk + t4 + 4) * BSTR + cb]);
#pragma unroll
                for (int mt = 0; mt < 4; mt++) mma8(acc[mt][nt], af[mt], b0, b1);
            }
        }
        __syncthreads();
        cur ^= 1;
    }

    // epilogue
#pragma unroll
    for (int mt = 0; mt < 4; mt++) {
        int r0 = m0 + wm + mt * 16 + g;
        int r1 = r0 + 8;
#pragma unroll
        for (int nt = 0; nt < 4; nt++) {
            int cb = n0 + wn + nt * 8 + 2 * t4;
            const float* a4 = acc[mt][nt];
#pragma unroll
            for (int half = 0; half < 2; half++) {
                int r = half ? r1 : r0;
                if (r >= M) continue;
                float bv = BIAS ? bias[r] : 0.f;
#pragma unroll
                for (int j = 0; j < 2; j++) {
                    size_t idx = (size_t)r * N + cb + j;
                    float v = a4[half * 2 + j] + bv;
                    if (RES) v += resp[idx];
                    if (ACCUM) v += C[idx];
                    if (ACT == 1) v = fmaxf(v, 0.f);
                    C[idx] = v;
                }
            }
        }
    }
}

// ---------------- attention logits + exp: S[i,j] = exp(sum_r Q[r,i]*K[r,j]) ----------------
__global__ void __launch_bounds__(256) attn_exp_k(
    const float* __restrict__ Q, const float* __restrict__ Km, float* __restrict__ S)
{
    int bz = blockIdx.z;
    Q  += (size_t)bz * RCQ * HWP;
    Km += (size_t)bz * RCQ * HWP;
    S  += (size_t)bz * HWP * (size_t)HWP;

    __shared__ float Qs[RCQ][64];
    __shared__ float Ks[RCQ][64];

    int i0 = blockIdx.y * 64, j0 = blockIdx.x * 64;
    int tid = threadIdx.x;
    for (int t = tid; t < RCQ * 64; t += 256) {
        int r = t >> 6, c = t & 63;
        Qs[r][c] = Q[(size_t)r * HWP + i0 + c];
        Ks[r][c] = Km[(size_t)r * HWP + j0 + c];
    }
    __syncthreads();

    int tx = tid % 16, ty = tid / 16;
    float acc[4][4];
#pragma unroll
    for (int i = 0; i < 4; i++)
#pragma unroll
        for (int j = 0; j < 4; j++) acc[i][j] = 0.f;

#pragma unroll
    for (int r = 0; r < RCQ; r++) {
        float q[4], k[4];
#pragma unroll
        for (int i = 0; i < 4; i++) q[i] = Qs[r][ty * 4 + i];
#pragma unroll
        for (int j = 0; j < 4; j++) k[j] = Ks[r][tx * 4 + j];
#pragma unroll
        for (int i = 0; i < 4; i++)
#pragma unroll
            for (int j = 0; j < 4; j++) acc[i][j] += q[i] * k[j];
    }
#pragma unroll
    for (int i = 0; i < 4; i++) {
        size_t row = (size_t)(i0 + ty * 4 + i) * HWP + j0 + tx * 4;
#pragma unroll
        for (int j = 0; j < 4; j++) S[row + j] = __expf(acc[i][j]);
    }
}

// ---------------- row sum -> 1/Z ----------------
__global__ void __launch_bounds__(256) rowsum_inv_k(
    const float* __restrict__ S, float* __restrict__ invZ)
{
    int i = blockIdx.x;
    int bz = blockIdx.y;
    const float* row = S + (size_t)bz * HWP * HWP + (size_t)i * HWP;
    float s = 0.f;
    for (int j = threadIdx.x; j < HWP; j += 256) s += row[j];
    __shared__ float red[256];
    red[threadIdx.x] = s;
    __syncthreads();
    for (int o = 128; o > 0; o >>= 1) {
        if (threadIdx.x < o) red[threadIdx.x] += red[threadIdx.x + o];
        __syncthreads();
    }
    if (threadIdx.x == 0) invZ[bz * HWP + i] = 1.f / red[0];
}

// ---------------- scale V rows by invZ over spatial index ----------------
__global__ void __launch_bounds__(256) scalev_k(float* __restrict__ v, const float* __restrict__ invZ)
{
    size_t idx = (size_t)blockIdx.x * 256 + threadIdx.x;   // NB*CC*HWP
    size_t n = idx / ((size_t)CC * HWP);
    size_t i = idx % (size_t)HWP;
    v[idx] *= invZ[n * HWP + i];
}

// ---------------- gated combine: f = [br*g + bd*(1-g); br*bd] ----------------
__global__ void __launch_bounds__(256) combine_k(
    const float* __restrict__ cat, const float* __restrict__ gpre, float* __restrict__ f)
{
    size_t idx = (size_t)blockIdx.x * 256 + threadIdx.x;   // NB*CC*HWP
    size_t n = idx / ((size_t)CC * HWP);
    size_t r = idx % ((size_t)CC * HWP);
    size_t base = n * (size_t)C2 * HWP;
    float a = cat[base + r];
    float b = cat[base + (size_t)CC * HWP + r];
    float gg = 1.f / (1.f + __expf(-gpre[idx]));
    f[base + r] = a * gg + b * (1.f - gg);
    f[base + (size_t)CC * HWP + r] = a * b;
}

// ---------------- im2col for 3x3 SAME conv: col[(ci*9+tap)][p] ----------------
__global__ void __launch_bounds__(256) im2col_k(
    const float* __restrict__ in, float* __restrict__ col)
{
    size_t idx = (size_t)blockIdx.x * 256 + threadIdx.x;   // NB*KCOL*HWP
    int p = (int)(idx % HWP);
    size_t t = idx / HWP;
    int row = (int)(t % KCOL);
    int n = (int)(t / KCOL);
    int tap = row % 9, ci = row / 9;
    int ky = tap / 3, kx = tap % 3;
    int y = p >> 6, x = p & 63;
    int yy = y + ky - 1, xx = x + kx - 1;
    float v = 0.f;
    if (yy >= 0 && yy < HH && xx >= 0 && xx < WW)
        v = in[(((size_t)n * C2 + ci) * HH + yy) * WW + xx];
    col[idx] = v;
}

// ---------------- host launcher ----------------
extern "C" void kernel_launch(void* const* d_in, const int* in_sizes, int n_in,
                              void* d_out, int out_size)
{
    const float* rgb  = (const float*)d_in[0];
    const float* chm  = (const float*)d_in[1];
    const float* rq_w = (const float*)d_in[2];  const float* rq_b = (const float*)d_in[3];
    const float* rk_w = (const float*)d_in[4];  const float* rk_b = (const float*)d_in[5];
    const float* rv_w = (const float*)d_in[6];  const float* rv_b = (const float*)d_in[7];
    const float* dq_w = (const float*)d_in[8];  const float* dq_b = (const float*)d_in[9];
    const float* dk_w = (const float*)d_in[10]; const float* dk_b = (const float*)d_in[11];
    const float* dv_w = (const float*)d_in[12]; const float* dv_b = (const float*)d_in[13];
    const float* gate_w = (const float*)d_in[14]; const float* gate_b = (const float*)d_in[15];
    const float* fus1_w = (const float*)d_in[16]; const float* fus1_b = (const float*)d_in[17];
    const float* fus2_w = (const float*)d_in[18]; const float* fus2_b = (const float*)d_in[19];
    const float* fus3_w = (const float*)d_in[20]; const float* fus3_b = (const float*)d_in[21];
    const float* skip_w = (const float*)d_in[22]; const float* skip_b = (const float*)d_in[23];
    float* out = (float*)d_out;

    float *rq, *rk, *dq, *dk, *rv, *dv, *S, *invZ, *cat, *gate, *f, *y1, *y2, *col;
    cudaGetSymbolAddress((void**)&rq, g_rq);
    cudaGetSymbolAddress((void**)&rk, g_rk);
    cudaGetSymbolAddress((void**)&dq, g_dq);
    cudaGetSymbolAddress((void**)&dk, g_dk);
    cudaGetSymbolAddress((void**)&rv, g_rv);
    cudaGetSymbolAddress((void**)&dv, g_dv);
    cudaGetSymbolAddress((void**)&S, g_S);
    cudaGetSymbolAddress((void**)&invZ, g_invZ);
    cudaGetSymbolAddress((void**)&cat, g_cat);
    cudaGetSymbolAddress((void**)&gate, g_gate);
    cudaGetSymbolAddress((void**)&f, g_f);
    cudaGetSymbolAddress((void**)&y1, g_y1);
    cudaGetSymbolAddress((void**)&y2, g_y2);
    cudaGetSymbolAddress((void**)&col, g_col);

    // raise dynamic smem limit for each instantiation (idempotent, capture-safe)
    cudaFuncSetAttribute(tgemm_k<false, 0, false, true>,  cudaFuncAttributeMaxDynamicSharedMemorySize, SMEM_BYTES);
    cudaFuncSetAttribute(tgemm_k<false, 0, true,  false>, cudaFuncAttributeMaxDynamicSharedMemorySize, SMEM_BYTES);
    cudaFuncSetAttribute(tgemm_k<false, 1, false, true>,  cudaFuncAttributeMaxDynamicSharedMemorySize, SMEM_BYTES);
    cudaFuncSetAttribute(tgemm_k<true,  0, false, true>,  cudaFuncAttributeMaxDynamicSharedMemorySize, SMEM_BYTES);

    dim3 blk(256);
    auto grid_mn = [](int M, int N) {
        return dim3((unsigned)(N / 128), (unsigned)((M + 127) / 128), NB);
    };
    const size_t sX = (size_t)CC * HWP;
    const size_t sQ = (size_t)RCQ * HWP;
    const size_t sS = (size_t)HWP * HWP;
    const size_t sF = (size_t)C2 * HWP;
    const size_t sCol = (size_t)KCOL * HWP;

    // --- projections (1x1 convs as TF32 GEMMs) ---
    tgemm_k<false, 0, false, true><<<grid_mn(RCQ, HWP), blk, SMEM_BYTES>>>(
        rq_w, CC, 0, rgb, HWP, sX, rq, sQ, rq_b, nullptr, 0, RCQ, HWP, CC);
    tgemm_k<false, 0, false, true><<<grid_mn(RCQ, HWP), blk, SMEM_BYTES>>>(
        rk_w, CC, 0, rgb, HWP, sX, rk, sQ, rk_b, nullptr, 0, RCQ, HWP, CC);
    tgemm_k<false, 0, false, true><<<grid_mn(CC, HWP), blk, SMEM_BYTES>>>(
        rv_w, CC, 0, rgb, HWP, sX, rv, sX, rv_b, nullptr, 0, CC, HWP, CC);
    tgemm_k<false, 0, false, true><<<grid_mn(RCQ, HWP), blk, SMEM_BYTES>>>(
        dq_w, CC, 0, chm, HWP, sX, dq, sQ, dq_b, nullptr, 0, RCQ, HWP, CC);
    tgemm_k<false, 0, false, true><<<grid_mn(RCQ, HWP), blk, SMEM_BYTES>>>(
        dk_w, CC, 0, chm, HWP, sX, dk, sQ, dk_b, nullptr, 0, RCQ, HWP, CC);
    tgemm_k<false, 0, false, true><<<grid_mn(CC, HWP), blk, SMEM_BYTES>>>(
        dv_w, CC, 0, chm, HWP, sX, dv, sX, dv_b, nullptr, 0, CC, HWP, CC);

    // --- attention R: br = rv @ softmax(dq.dk) + rgb  -> cat[:,0:C] ---
    attn_exp_k<<<dim3(64, 64, NB), blk>>>(dq, dk, S);
    rowsum_inv_k<<<dim3(HWP, NB), blk>>>(S, invZ);
    scalev_k<<<(unsigned)(((size_t)NB * CC * HWP) / 256), blk>>>(rv, invZ);
    tgemm_k<false, 0, true, false><<<grid_mn(CC, HWP), blk, SMEM_BYTES>>>(
        rv, HWP, sX, S, HWP, sS, cat, sF, nullptr, rgb, sX, CC, HWP, HWP);

    // --- attention D: bd = dv @ softmax(rq.rk) + chm  -> cat[:,C:2C] ---
    attn_exp_k<<<dim3(64, 64, NB), blk>>>(rq, rk, S);
    rowsum_inv_k<<<dim3(HWP, NB), blk>>>(S, invZ);
    scalev_k<<<(unsigned)(((size_t)NB * CC * HWP) / 256), blk>>>(dv, invZ);
    tgemm_k<false, 0, true, false><<<grid_mn(CC, HWP), blk, SMEM_BYTES>>>(
        dv, HWP, sX, S, HWP, sS, cat + sX, sF, nullptr, chm, sX, CC, HWP, HWP);

    // --- gate pre-activation: single GEMM over cat (K=2C) ---
    tgemm_k<false, 0, false, true><<<grid_mn(CC, HWP), blk, SMEM_BYTES>>>(
        gate_w, C2, 0, cat, HWP, sF, gate, sX, gate_b, nullptr, 0, CC, HWP, C2);

    // --- gated fusion -> f = [c_fused; d_fused] ---
    combine_k<<<(unsigned)(((size_t)NB * CC * HWP) / 256), blk>>>(cat, gate, f);

    // --- fus1: y1 = relu(W1 @ f + b1) ---
    tgemm_k<false, 1, false, true><<<grid_mn(C2, HWP), blk, SMEM_BYTES>>>(
        fus1_w, C2, 0, f, HWP, sF, y1, sF, fus1_b, nullptr, 0, C2, HWP, C2);

    // --- fus2: im2col + TF32 GEMM (K=4608), relu+bias ---
    im2col_k<<<(unsigned)(((size_t)NB * KCOL * HWP) / 256), blk>>>(y1, col);
    tgemm_k<false, 1, false, true><<<grid_mn(C2, HWP), blk, SMEM_BYTES>>>(
        fus2_w, KCOL, 0, col, HWP, sCol, y2, sF, fus2_b, nullptr, 0, C2, HWP, KCOL);

    // --- head: out = W3 @ y2 + b3 + Wskip @ f + bskip ---
    tgemm_k<false, 0, false, true><<<grid_mn(CC, HWP), blk, SMEM_BYTES>>>(
        fus3_w, C2, 0, y2, HWP, sF, out, sX, fus3_b, nullptr, 0, CC, HWP, C2);
    tgemm_k<true, 0, false, true><<<grid_mn(CC, HWP), blk, SMEM_BYTES>>>(
        skip_w, C2, 0, f, HWP, sF, out, sX, skip_b, nullptr, 0, CC, HWP, C2);

    (void)in_sizes; (void)n_in; (void)out_size;
}

// round 5
// speedup vs baseline: 4.7831x; 1.1842x over previous
#include <cuda_runtime.h>
#include <cstdint>
#include <math.h>

#define NB 2
#define CC 256
#define RCQ 32
#define HH 64
#define WW 64
#define HWP 4096   // H*W
#define C2 512     // 2*C
#define KCOL 4608  // 512*9 (im2col K)
#define MPROJ 320  // 32+32+256 concatenated projection rows

// ---------------- scratch (device globals; no allocation allowed) ----------------
__device__ float g_projR[(size_t)NB * MPROJ * HWP];  // rows: 0-31 q, 32-63 k, 64-319 v
__device__ float g_projD[(size_t)NB * MPROJ * HWP];
__device__ float g_invZA[NB * HWP];
__device__ float g_invZB[NB * HWP];
__device__ float g_cat[(size_t)NB * C2 * HWP];       // [br ; bd]
__device__ float g_f[(size_t)NB * C2 * HWP];
__device__ float g_y1[(size_t)NB * C2 * HWP];
__device__ float g_y2[(size_t)NB * C2 * HWP];
__device__ float g_col[(size_t)NB * KCOL * HWP];     // im2col buffer
// pre-converted (tf32) weights
__device__ float g_wR[MPROJ * CC];
__device__ float g_wD[MPROJ * CC];
__device__ float g_bR[MPROJ];
__device__ float g_bD[MPROJ];
__device__ float g_wGate[CC * C2];
__device__ float g_wF1[C2 * C2];
__device__ float g_wF2[C2 * KCOL];
__device__ float g_wF3[CC * C2];
__device__ float g_wSkip[CC * C2];

// ---------------- helpers ----------------
__device__ __forceinline__ void cp16(uint32_t dst, const void* src, bool v) {
    int sz = v ? 16 : 0;
    asm volatile("cp.async.cg.shared.global [%0], [%1], 16, %2;\n"
                 :: "r"(dst), "l"(src), "r"(sz));
}
__device__ __forceinline__ uint32_t cvt_tf32(float x) {
    uint32_t r;
    asm("cvt.rna.tf32.f32 %0, %1;" : "=r"(r) : "f"(x));
    return r;
}
__device__ __forceinline__ float tf32f(float x) { return __uint_as_float(cvt_tf32(x)); }
__device__ __forceinline__ void mma8(float* c, const uint32_t* a, uint32_t b0, uint32_t b1) {
    asm volatile(
        "mma.sync.aligned.m16n8k8.row.col.f32.tf32.tf32.f32 "
        "{%0,%1,%2,%3}, {%4,%5,%6,%7}, {%8,%9}, {%0,%1,%2,%3};"
        : "+f"(c[0]), "+f"(c[1]), "+f"(c[2]), "+f"(c[3])
        : "r"(a[0]), "r"(a[1]), "r"(a[2]), "r"(a[3]), "r"(b0), "r"(b1));
}

// weight pre-conversion to tf32
__global__ void __launch_bounds__(256) cvtcopy_k(const float* __restrict__ s, float* __restrict__ d) {
    int i = blockIdx.x * 256 + threadIdx.x;
    d[i] = __uint_as_float(cvt_tf32(s[i]));
}

// ---------------- TF32 tensor-core GEMM ----------------
#define FL_ACC  1
#define FL_RELU 2
#define FL_BIAS 8
#define FL_GATE 16
#define FL_NCA  32
#define FL_NCB  64
#define FL_CVTO 128

#define ASTR 36
#define BSTR 136
#define ABUF (128 * ASTR)
#define BBUF (32 * BSTR)
#define SMEM_BYTES ((2 * ABUF + 2 * BBUF) * 4)   // 71680

template <int F>
__global__ void __launch_bounds__(256, 2) tgemm_k(
    const float* __restrict__ A, int lda, size_t sA,
    const float* __restrict__ B, int ldb, size_t sB,
    float* __restrict__ C, size_t sC,
    const float* __restrict__ bias,
    const float* __restrict__ res, size_t sRes,
    int M, int N, int K)
{
    extern __shared__ float sm[];
    int bz = blockIdx.z;
    A += (size_t)bz * sA;
    B += (size_t)bz * sB;
    C += (size_t)bz * sC;
    const float* resp = res ? res + (size_t)bz * sRes : nullptr;

    const int m0 = blockIdx.y * 128, n0 = blockIdx.x * 128;
    const int tid = threadIdx.x;
    const int lane = tid & 31, warp = tid >> 5;
    const int g = lane >> 2, t4 = lane & 3;
    const int wm = (warp >> 2) * 64;
    const int wn = (warp & 3) * 32;

    const uint32_t sbase = (uint32_t)__cvta_generic_to_shared(sm);

    float acc[4][4][4];
#pragma unroll
    for (int mt = 0; mt < 4; mt++)
#pragma unroll
        for (int nt = 0; nt < 4; nt++)
#pragma unroll
            for (int i = 0; i < 4; i++) acc[mt][nt][i] = 0.f;

    auto loadA = [&](int buf, int k0) {
#pragma unroll
        for (int i = 0; i < 4; i++) {
            int c = tid + i * 256;
            int m = c >> 3, kg = c & 7;
            bool v = (m0 + m) < M;
            int mm = v ? (m0 + m) : 0;
            const float* src = A + (size_t)mm * lda + k0 + kg * 4;
            uint32_t dst = sbase + (uint32_t)((buf * ABUF + m * ASTR + kg * 4) * 4);
            cp16(dst, src, v);
        }
    };
    auto loadB = [&](int buf, int k0) {
#pragma unroll
        for (int i = 0; i < 4; i++) {
            int c = tid + i * 256;
            int k = c >> 5, ng = c & 31;
            const float* src = B + (size_t)(k0 + k) * ldb + n0 + ng * 4;
            uint32_t dst = sbase + (uint32_t)((2 * ABUF + buf * BBUF + k * BSTR + ng * 4) * 4);
            cp16(dst, src, true);
        }
    };

    const int KT = K / 32;
    loadA(0, 0);
    loadB(0, 0);
    asm volatile("cp.async.commit_group;\n");

    int cur = 0;
    for (int kt = 0; kt < KT; kt++) {
        if (kt + 1 < KT) {
            loadA(cur ^ 1, (kt + 1) * 32);
            loadB(cur ^ 1, (kt + 1) * 32);
            asm volatile("cp.async.commit_group;\n");
            asm volatile("cp.async.wait_group 1;\n");
        } else {
            asm volatile("cp.async.wait_group 0;\n");
        }
        __syncthreads();

        const float* Ab = sm + cur * ABUF;
        const float* Bb = sm + 2 * ABUF + cur * BBUF;
#pragma unroll
        for (int ks = 0; ks < 4; ks++) {
            const int kk = ks * 8;
            uint32_t af[4][4];
#pragma unroll
            for (int mt = 0; mt < 4; mt++) {
                int r0 = wm + mt * 16 + g;
                if (F & FL_NCA) {
                    af[mt][0] = __float_as_uint(Ab[r0 * ASTR + kk + t4]);
                    af[mt][1] = __float_as_uint(Ab[(r0 + 8) * ASTR + kk + t4]);
                    af[mt][2] = __float_as_uint(Ab[r0 * ASTR + kk + t4 + 4]);
                    af[mt][3] = __float_as_uint(Ab[(r0 + 8) * ASTR + kk + t4 + 4]);
                } else {
                    af[mt][0] = cvt_tf32(Ab[r0 * ASTR + kk + t4]);
                    af[mt][1] = cvt_tf32(Ab[(r0 + 8) * ASTR + kk + t4]);
                    af[mt][2] = cvt_tf32(Ab[r0 * ASTR + kk + t4 + 4]);
                    af[mt][3] = cvt_tf32(Ab[(r0 + 8) * ASTR + kk + t4 + 4]);
                }
            }
#pragma unroll
            for (int nt = 0; nt < 4; nt++) {
                int cb = wn + nt * 8 + g;
                uint32_t b0, b1;
                if (F & FL_NCB) {
                    b0 = __float_as_uint(Bb[(kk + t4) * BSTR + cb]);
                    b1 = __float_as_uint(Bb[(kk + t4 + 4) * BSTR + cb]);
                } else {
                    b0 = cvt_tf32(Bb[(kk + t4) * BSTR + cb]);
                    b1 = cvt_tf32(Bb[(kk + t4 + 4) * BSTR + cb]);
                }
#pragma unroll
                for (int mt = 0; mt < 4; mt++) mma8(acc[mt][nt], af[mt], b0, b1);
            }
        }
        __syncthreads();
        cur ^= 1;
    }

    // epilogue
#pragma unroll
    for (int mt = 0; mt < 4; mt++) {
        int r0 = m0 + wm + mt * 16 + g;
#pragma unroll
        for (int nt = 0; nt < 4; nt++) {
            int cb = n0 + wn + nt * 8 + 2 * t4;
            const float* a4 = acc[mt][nt];
#pragma unroll
            for (int half = 0; half < 2; half++) {
                int r = r0 + half * 8;
                if (r >= M) continue;
                float bv = (F & FL_BIAS) ? bias[r] : 0.f;
#pragma unroll
                for (int j = 0; j < 2; j++) {
                    size_t idx = (size_t)r * N + cb + j;
                    float v = a4[half * 2 + j] + bv;
                    if (F & FL_GATE) {
                        float a = resp[idx];
                        float b2 = resp[idx + (size_t)CC * N];
                        float gg = 1.f / (1.f + __expf(-v));
                        C[idx] = tf32f(a * gg + b2 * (1.f - gg));
                        C[idx + (size_t)CC * N] = tf32f(a * b2);
                    } else {
                        if (F & FL_ACC) v += C[idx];
                        if (F & FL_RELU) v = fmaxf(v, 0.f);
                        if (F & FL_CVTO) v = tf32f(v);
                        C[idx] = v;
                    }
                }
            }
        }
    }
}

#define P_PROJ (FL_BIAS | FL_NCA | FL_CVTO)
#define P_GATE (FL_BIAS | FL_NCA | FL_NCB | FL_GATE)
#define P_FUS  (FL_BIAS | FL_NCA | FL_NCB | FL_RELU | FL_CVTO)
#define P_FUS3 (FL_BIAS | FL_NCA | FL_NCB)
#define P_SKIP (FL_BIAS | FL_NCA | FL_NCB | FL_ACC)

// ---------------- attention pass 1: invZ[i] = 1/sum_j exp(S[i,j]) ----------------
// S[i,j] = sum_r Q[r,i]*K[r,j]. Block = 64 i-rows, loops all j in 128-chunks.
__global__ void __launch_bounds__(256) attn_z_k(
    const float* __restrict__ Q, const float* __restrict__ Kmat,
    float* __restrict__ invZ, size_t sP)
{
    __shared__ float dqT[64 * 36];
    __shared__ float dkS[2 * 32 * 136];
    __shared__ float zred[4][64];

    const int bz = blockIdx.y;
    const int i0 = blockIdx.x * 64;
    Q    += (size_t)bz * sP;
    Kmat += (size_t)bz * sP;
    invZ += (size_t)bz * HWP;

    const int tid = threadIdx.x;
    const int lane = tid & 31, warp = tid >> 5;
    const int g = lane >> 2, t4 = lane & 3;
    const uint32_t dkbase = (uint32_t)__cvta_generic_to_shared(dkS);

    // transpose-load Q tile: [64 i][32 r]
#pragma unroll
    for (int rep = 0; rep < 8; rep++) {
        int idx = tid + rep * 256;
        int r = idx >> 6, ii = idx & 63;
        dqT[ii * 36 + r] = Q[(size_t)r * HWP + i0 + ii];
    }
    auto loadK = [&](int buf, int j0) {
#pragma unroll
        for (int rep = 0; rep < 4; rep++) {
            int c = tid + rep * 256;
            int r = c >> 5, jg = c & 31;
            const float* src = Kmat + (size_t)r * HWP + j0 + jg * 4;
            uint32_t dst = dkbase + (uint32_t)((buf * 32 * 136 + r * 136 + jg * 4) * 4);
            cp16(dst, src, true);
        }
    };
    loadK(0, 0);
    asm volatile("cp.async.commit_group;\n");

    float zacc[2][2] = {{0.f, 0.f}, {0.f, 0.f}};
    const int wm = (warp >> 2) * 32, wn = (warp & 3) * 32;

    for (int jc = 0; jc < 32; jc++) {
        int cur = jc & 1;
        asm volatile("cp.async.wait_group 0;\n");
        __syncthreads();
        if (jc + 1 < 32) {
            loadK(cur ^ 1, (jc + 1) * 128);
            asm volatile("cp.async.commit_group;\n");
        }
        const float* dk = dkS + cur * 32 * 136;
        float sacc[2][4][4];
#pragma unroll
        for (int mt = 0; mt < 2; mt++)
#pragma unroll
            for (int nt = 0; nt < 4; nt++)
#pragma unroll
                for (int e = 0; e < 4; e++) sacc[mt][nt][e] = 0.f;
#pragma unroll
        for (int ks = 0; ks < 4; ks++) {
            int kk = ks * 8;
            uint32_t a[2][4];
#pragma unroll
            for (int mt = 0; mt < 2; mt++) {
                int r0 = wm + mt * 16 + g;
                a[mt][0] = __float_as_uint(dqT[r0 * 36 + kk + t4]);
                a[mt][1] = __float_as_uint(dqT[(r0 + 8) * 36 + kk + t4]);
                a[mt][2] = __float_as_uint(dqT[r0 * 36 + kk + t4 + 4]);
                a[mt][3] = __float_as_uint(dqT[(r0 + 8) * 36 + kk + t4 + 4]);
            }
#pragma unroll
            for (int nt = 0; nt < 4; nt++) {
                int cb = wn + nt * 8 + g;
                uint32_t b0 = __float_as_uint(dk[(kk + t4) * 136 + cb]);
                uint32_t b1 = __float_as_uint(dk[(kk + t4 + 4) * 136 + cb]);
#pragma unroll
                for (int mt = 0; mt < 2; mt++) mma8(sacc[mt][nt], a[mt], b0, b1);
            }
        }
#pragma unroll
        for (int mt = 0; mt < 2; mt++)
#pragma unroll
            for (int nt = 0; nt < 4; nt++) {
                zacc[mt][0] += __expf(sacc[mt][nt][0]) + __expf(sacc[mt][nt][1]);
                zacc[mt][1] += __expf(sacc[mt][nt][2]) + __expf(sacc[mt][nt][3]);
            }
    }
    // reduce over t4 lanes, then across the 4 n-warps
#pragma unroll
    for (int mt = 0; mt < 2; mt++)
#pragma unroll
        for (int h = 0; h < 2; h++) {
            float v = zacc[mt][h];
            v += __shfl_xor_sync(0xffffffffu, v, 1);
            v += __shfl_xor_sync(0xffffffffu, v, 2);
            if (t4 == 0) zred[warp & 3][wm + mt * 16 + h * 8 + g] = v;
        }
    __syncthreads();
    if (tid < 64) {
        float s = zred[0][tid] + zred[1][tid] + zred[2][tid] + zred[3][tid];
        invZ[i0 + tid] = 1.f / s;
    }
}

// ---------------- attention pass 2: out[c,j] = sum_i V[c,i]*exp(S[i,j])*invZ[i] + res ----
#define AP_DKT 0
#define AP_DQ  (128 * 36)
#define AP_RV  (AP_DQ + 2 * 32 * 40)
#define AP_ES  (AP_RV + 2 * 128 * 36)
#define AP_SMEM_BYTES ((AP_ES + 32 * 136) * 4)   // 82944

__global__ void __launch_bounds__(256) attn_apply_k(
    const float* __restrict__ Q, const float* __restrict__ Km,
    const float* __restrict__ V, const float* __restrict__ invZ,
    const float* __restrict__ res, float* __restrict__ out,
    size_t sP, size_t sOut)
{
    extern __shared__ float sm[];
    float* dkT = sm + AP_DKT;   // [128 j][36]
    float* eS  = sm + AP_ES;    // [32 i][136]

    const int bz = blockIdx.z;
    const int j0 = blockIdx.x * 128;
    const int c0 = blockIdx.y * 128;
    Q    += (size_t)bz * sP;
    Km   += (size_t)bz * sP;
    V    += (size_t)bz * sP + (size_t)c0 * HWP;
    invZ += (size_t)bz * HWP;
    res  += (size_t)bz * (size_t)CC * HWP + (size_t)c0 * HWP;
    out  += (size_t)bz * sOut + (size_t)c0 * HWP;

    const int tid = threadIdx.x;
    const int lane = tid & 31, warp = tid >> 5;
    const int g = lane >> 2, t4 = lane & 3;
    const uint32_t sbase = (uint32_t)__cvta_generic_to_shared(sm);

    // transpose-load K tile once: [128 j][32 r]
#pragma unroll
    for (int rep = 0; rep < 16; rep++) {
        int idx = tid + rep * 256;
        int r = idx >> 7, jj = idx & 127;
        dkT[jj * 36 + r] = Km[(size_t)r * HWP + j0 + jj];
    }

    auto loadQ = [&](int buf, int i0) {
        int r = tid >> 3, ig = tid & 7;
        const float* src = Q + (size_t)r * HWP + i0 + ig * 4;
        uint32_t dst = sbase + (uint32_t)((AP_DQ + buf * 32 * 40 + r * 40 + ig * 4) * 4);
        cp16(dst, src, true);
    };
    auto loadV = [&](int buf, int i0) {
#pragma unroll
        for (int rep = 0; rep < 4; rep++) {
            int c = tid + rep * 256;
            int row = c >> 3, ig = c & 7;
            const float* src = V + (size_t)row * HWP + i0 + ig * 4;
            uint32_t dst = sbase + (uint32_t)((AP_RV + buf * 128 * 36 + row * 36 + ig * 4) * 4);
            cp16(dst, src, true);
        }
    };
    loadQ(0, 0);
    loadV(0, 0);
    asm volatile("cp.async.commit_group;\n");

    float acc[4][4][4];
#pragma unroll
    for (int mt = 0; mt < 4; mt++)
#pragma unroll
        for (int nt = 0; nt < 4; nt++)
#pragma unroll
            for (int e = 0; e < 4; e++) acc[mt][nt][e] = 0.f;

    const int wj = warp * 16;
    const int wm = (warp >> 2) * 64, wn = (warp & 3) * 32;

    for (int ic = 0; ic < 128; ic++) {
        const int i0 = ic * 32;
        const int cur = ic & 1;
        asm volatile("cp.async.wait_group 0;\n");
        __syncthreads();          // buffers ready + prev phase-B done (eS reusable)
        if (ic + 1 < 128) {
            loadQ(cur ^ 1, i0 + 32);
            loadV(cur ^ 1, i0 + 32);
            asm volatile("cp.async.commit_group;\n");
        }
        // ---- phase A: S'[j (m=128), i (n=32)] ----
        const float* dq = sm + AP_DQ + cur * 32 * 40;   // [32 r][40]
        float sacc[4][4];
#pragma unroll
        for (int nt = 0; nt < 4; nt++)
#pragma unroll
            for (int e = 0; e < 4; e++) sacc[nt][e] = 0.f;
#pragma unroll
        for (int ks = 0; ks < 4; ks++) {
            int kk = ks * 8;
            uint32_t a[4];
            a[0] = __float_as_uint(dkT[(wj + g) * 36 + kk + t4]);
            a[1] = __float_as_uint(dkT[(wj + g + 8) * 36 + kk + t4]);
            a[2] = __float_as_uint(dkT[(wj + g) * 36 + kk + t4 + 4]);
            a[3] = __float_as_uint(dkT[(wj + g + 8) * 36 + kk + t4 + 4]);
#pragma unroll
            for (int nt = 0; nt < 4; nt++) {
                int ci = nt * 8 + g;
                uint32_t b0 = __float_as_uint(dq[(kk + t4) * 40 + ci]);
                uint32_t b1 = __float_as_uint(dq[(kk + t4 + 4) * 40 + ci]);
                mma8(sacc[nt], a, b0, b1);
            }
        }
        // exp * invZ -> eS[i][j] (transposed store), pre-rounded to tf32
#pragma unroll
        for (int nt = 0; nt < 4; nt++) {
            int il = nt * 8 + 2 * t4;
            float iz0 = invZ[i0 + il];
            float iz1 = invZ[i0 + il + 1];
            eS[il * 136 + wj + g]           = tf32f(__expf(sacc[nt][0]) * iz0);
            eS[(il + 1) * 136 + wj + g]     = tf32f(__expf(sacc[nt][1]) * iz1);
            eS[il * 136 + wj + g + 8]       = tf32f(__expf(sacc[nt][2]) * iz0);
            eS[(il + 1) * 136 + wj + g + 8] = tf32f(__expf(sacc[nt][3]) * iz1);
        }
        __syncthreads();
        // ---- phase B: acc[c (m=128), j (n=128)] += V_tile @ eS ----
        const float* rv = sm + AP_RV + cur * 128 * 36;  // [128 c][36]
#pragma unroll
        for (int ks = 0; ks < 4; ks++) {
            int kk = ks * 8;
            uint32_t af[4][4];
#pragma unroll
            for (int mt = 0; mt < 4; mt++) {
                int r0 = wm + mt * 16 + g;
                af[mt][0] = __float_as_uint(rv[r0 * 36 + kk + t4]);
                af[mt][1] = __float_as_uint(rv[(r0 + 8) * 36 + kk + t4]);
                af[mt][2] = __float_as_uint(rv[r0 * 36 + kk + t4 + 4]);
                af[mt][3] = __float_as_uint(rv[(r0 + 8) * 36 + kk + t4 + 4]);
            }
#pragma unroll
            for (int nt = 0; nt < 4; nt++) {
                int cb = wn + nt * 8 + g;
                uint32_t b0 = __float_as_uint(eS[(kk + t4) * 136 + cb]);
                uint32_t b1 = __float_as_uint(eS[(kk + t4 + 4) * 136 + cb]);
#pragma unroll
                for (int mt = 0; mt < 4; mt++) mma8(acc[mt][nt], af[mt], b0, b1);
            }
        }
    }
    // epilogue: + residual, round to tf32 (cat feeds only tf32 GEMM operands)
#pragma unroll
    for (int mt = 0; mt < 4; mt++)
#pragma unroll
        for (int nt = 0; nt < 4; nt++)
#pragma unroll
            for (int e = 0; e < 4; e++) {
                int row = wm + mt * 16 + g + (e >> 1) * 8;
                int col = j0 + wn + nt * 8 + 2 * t4 + (e & 1);
                size_t o = (size_t)row * HWP + col;
                out[o] = tf32f(acc[mt][nt][e] + res[o]);
            }
}

// ---------------- im2col for 3x3 SAME conv ----------------
__global__ void __launch_bounds__(256) im2col_k(
    const float* __restrict__ in, float* __restrict__ col)
{
    size_t idx = (size_t)blockIdx.x * 256 + threadIdx.x;
    int p = (int)(idx % HWP);
    size_t t = idx / HWP;
    int row = (int)(t % KCOL);
    int n = (int)(t / KCOL);
    int tap = row % 9, ci = row / 9;
    int ky = tap / 3, kx = tap % 3;
    int y = p >> 6, x = p & 63;
    int yy = y + ky - 1, xx = x + kx - 1;
    float v = 0.f;
    if (yy >= 0 && yy < HH && xx >= 0 && xx < WW)
        v = in[(((size_t)n * C2 + ci) * HH + yy) * WW + xx];
    col[idx] = v;
}

// ---------------- host launcher ----------------
extern "C" void kernel_launch(void* const* d_in, const int* in_sizes, int n_in,
                              void* d_out, int out_size)
{
    const float* rgb  = (const float*)d_in[0];
    const float* chm  = (const float*)d_in[1];
    const float* rq_w = (const float*)d_in[2];  const float* rq_b = (const float*)d_in[3];
    const float* rk_w = (const float*)d_in[4];  const float* rk_b = (const float*)d_in[5];
    const float* rv_w = (const float*)d_in[6];  const float* rv_b = (const float*)d_in[7];
    const float* dq_w = (const float*)d_in[8];  const float* dq_b = (const float*)d_in[9];
    const float* dk_w = (const float*)d_in[10]; const float* dk_b = (const float*)d_in[11];
    const float* dv_w = (const float*)d_in[12]; const float* dv_b = (const float*)d_in[13];
    const float* gate_w = (const float*)d_in[14]; const float* gate_b = (const float*)d_in[15];
    const float* fus1_w = (const float*)d_in[16]; const float* fus1_b = (const float*)d_in[17];
    const float* fus2_w = (const float*)d_in[18]; const float* fus2_b = (const float*)d_in[19];
    const float* fus3_w = (const float*)d_in[20]; const float* fus3_b = (const float*)d_in[21];
    const float* skip_w = (const float*)d_in[22]; const float* skip_b = (const float*)d_in[23];
    float* out = (float*)d_out;

    float *projR, *projD, *invZA, *invZB, *cat, *f, *y1, *y2, *col;
    float *wR, *wD, *bR, *bD, *wGate, *wF1, *wF2, *wF3, *wSkip;
    cudaGetSymbolAddress((void**)&projR, g_projR);
    cudaGetSymbolAddress((void**)&projD, g_projD);
    cudaGetSymbolAddress((void**)&invZA, g_invZA);
    cudaGetSymbolAddress((void**)&invZB, g_invZB);
    cudaGetSymbolAddress((void**)&cat, g_cat);
    cudaGetSymbolAddress((void**)&f, g_f);
    cudaGetSymbolAddress((void**)&y1, g_y1);
    cudaGetSymbolAddress((void**)&y2, g_y2);
    cudaGetSymbolAddress((void**)&col, g_col);
    cudaGetSymbolAddress((void**)&wR, g_wR);
    cudaGetSymbolAddress((void**)&wD, g_wD);
    cudaGetSymbolAddress((void**)&bR, g_bR);
    cudaGetSymbolAddress((void**)&bD, g_bD);
    cudaGetSymbolAddress((void**)&wGate, g_wGate);
    cudaGetSymbolAddress((void**)&wF1, g_wF1);
    cudaGetSymbolAddress((void**)&wF2, g_wF2);
    cudaGetSymbolAddress((void**)&wF3, g_wF3);
    cudaGetSymbolAddress((void**)&wSkip, g_wSkip);

    cudaFuncSetAttribute(tgemm_k<P_PROJ>, cudaFuncAttributeMaxDynamicSharedMemorySize, SMEM_BYTES);
    cudaFuncSetAttribute(tgemm_k<P_GATE>, cudaFuncAttributeMaxDynamicSharedMemorySize, SMEM_BYTES);
    cudaFuncSetAttribute(tgemm_k<P_FUS>,  cudaFuncAttributeMaxDynamicSharedMemorySize, SMEM_BYTES);
    cudaFuncSetAttribute(tgemm_k<P_FUS3>, cudaFuncAttributeMaxDynamicSharedMemorySize, SMEM_BYTES);
    cudaFuncSetAttribute(tgemm_k<P_SKIP>, cudaFuncAttributeMaxDynamicSharedMemorySize, SMEM_BYTES);
    cudaFuncSetAttribute(attn_apply_k, cudaFuncAttributeMaxDynamicSharedMemorySize, AP_SMEM_BYTES);

    dim3 blk(256);
    const size_t sX = (size_t)CC * HWP;
    const size_t sF = (size_t)C2 * HWP;
    const size_t sP = (size_t)MPROJ * HWP;
    const size_t sCol = (size_t)KCOL * HWP;

    // --- pre-convert weights to tf32 (concatenating projections) ---
    cvtcopy_k<<<RCQ * CC / 256, blk>>>(rq_w, wR);
    cvtcopy_k<<<RCQ * CC / 256, blk>>>(rk_w, wR + RCQ * CC);
    cvtcopy_k<<<CC * CC / 256, blk>>>(rv_w, wR + 2 * RCQ * CC);
    cvtcopy_k<<<RCQ * CC / 256, blk>>>(dq_w, wD);
    cvtcopy_k<<<RCQ * CC / 256, blk>>>(dk_w, wD + RCQ * CC);
    cvtcopy_k<<<CC * CC / 256, blk>>>(dv_w, wD + 2 * RCQ * CC);
    cvtcopy_k<<<CC * C2 / 256, blk>>>(gate_w, wGate);
    cvtcopy_k<<<C2 * C2 / 256, blk>>>(fus1_w, wF1);
    cvtcopy_k<<<C2 * KCOL / 256, blk>>>(fus2_w, wF2);
    cvtcopy_k<<<CC * C2 / 256, blk>>>(fus3_w, wF3);
    cvtcopy_k<<<CC * C2 / 256, blk>>>(skip_w, wSkip);
    cudaMemcpyAsync(bR, rq_b, RCQ * 4, cudaMemcpyDeviceToDevice);
    cudaMemcpyAsync(bR + RCQ, rk_b, RCQ * 4, cudaMemcpyDeviceToDevice);
    cudaMemcpyAsync(bR + 2 * RCQ, rv_b, CC * 4, cudaMemcpyDeviceToDevice);
    cudaMemcpyAsync(bD, dq_b, RCQ * 4, cudaMemcpyDeviceToDevice);
    cudaMemcpyAsync(bD + RCQ, dk_b, RCQ * 4, cudaMemcpyDeviceToDevice);
    cudaMemcpyAsync(bD + 2 * RCQ, dv_b, CC * 4, cudaMemcpyDeviceToDevice);

    // --- batched projections: [q;k;v] = W @ x, outputs rounded to tf32 ---
    tgemm_k<P_PROJ><<<dim3(32, 3, NB), blk, SMEM_BYTES>>>(
        wR, CC, 0, rgb, HWP, sX, projR, sP, bR, nullptr, 0, MPROJ, HWP, CC);
    tgemm_k<P_PROJ><<<dim3(32, 3, NB), blk, SMEM_BYTES>>>(
        wD, CC, 0, chm, HWP, sX, projD, sP, bD, nullptr, 0, MPROJ, HWP, CC);

    const float* rq = projR;
    const float* rk = projR + RCQ * HWP;
    const float* rv = projR + 2 * RCQ * HWP;
    const float* dq = projD;
    const float* dk = projD + RCQ * HWP;
    const float* dv = projD + 2 * RCQ * HWP;

    // --- attention pass 1 (Z) for both attentions ---
    attn_z_k<<<dim3(64, NB), blk>>>(dq, dk, invZA, sP);   // rgb_attn = softmax(dq.dk)
    attn_z_k<<<dim3(64, NB), blk>>>(rq, rk, invZB, sP);   // depth_attn = softmax(rq.rk)

    // --- attention pass 2 (fused apply + residual) -> cat ---
    attn_apply_k<<<dim3(32, 2, NB), blk, AP_SMEM_BYTES>>>(
        dq, dk, rv, invZA, rgb, cat, sP, sF);             // br
    attn_apply_k<<<dim3(32, 2, NB), blk, AP_SMEM_BYTES>>>(
        rq, rk, dv, invZB, chm, cat + sX, sP, sF);        // bd

    // --- gate GEMM with fused sigmoid-gated combine -> f ---
    tgemm_k<P_GATE><<<dim3(32, 2, NB), blk, SMEM_BYTES>>>(
        wGate, C2, 0, cat, HWP, sF, f, sF, gate_b, cat, sF, CC, HWP, C2);

    // --- fus1: y1 = relu(W1 @ f + b1) ---
    tgemm_k<P_FUS><<<dim3(32, 4, NB), blk, SMEM_BYTES>>>(
        wF1, C2, 0, f, HWP, sF, y1, sF, fus1_b, nullptr, 0, C2, HWP, C2);

    // --- fus2: im2col + GEMM (K=4608), relu+bias ---
    im2col_k<<<(unsigned)(((size_t)NB * KCOL * HWP) / 256), blk>>>(y1, col);
    tgemm_k<P_FUS><<<dim3(32, 4, NB), blk, SMEM_BYTES>>>(
        wF2, KCOL, 0, col, HWP, sCol, y2, sF, fus2_b, nullptr, 0, C2, HWP, KCOL);

    // --- head: out = W3 @ y2 + b3 + Wskip @ f + bskip ---
    tgemm_k<P_FUS3><<<dim3(32, 2, NB), blk, SMEM_BYTES>>>(
        wF3, C2, 0, y2, HWP, sF, out, sX, fus3_b, nullptr, 0, CC, HWP, C2);
    tgemm_k<P_SKIP><<<dim3(32, 2, NB), blk, SMEM_BYTES>>>(
        wSkip, C2, 0, f, HWP, sF, out, sX, skip_b, nullptr, 0, CC, HWP, C2);

    (void)in_sizes; (void)n_in; (void)out_size;
}